// round 11
// baseline (speedup 1.0000x reference)
#include <cuda_runtime.h>
#include <cuda_bf16.h>
#include <cstdint>

#define B 8
#define D 256
#define HW (128 * 128)
#define C 80
#define NPIX (B * HW)
#define RANGE_EXTENDER 10.0f
#define EPS 1e-8f

#define KC 32                 // K per chunk
#define NT (D / KC)           // 8 chunks
#define PXT 128               // pixels per CTA (= M)
#define NTHREADS 256          // 8 warps: 4 px-groups x 2 ch-groups

// smem map (dynamic)
#define S_XR 0                // raw x staging: 16KB (single buffer)
#define S_XS 16384            // swizzled bf16 x: 2 x (xh 8KB + xl 8KB)
#define S_W  49152            // w image: 2 x 10240 (wh 5120 + wl 5120)
#define S_NP 69632            // norm partials 2*128*4
#define S_NI 70656            // inv norms 128*4
#define S_TOTAL 71168

// Pre-split weight image, 16B-swizzled: [chunk t][hl][c][64B]
__device__ __align__(16) unsigned char g_wimg[NT * 2 * C * 64];

// ---------------------------------------------------------------------------
// helpers
// ---------------------------------------------------------------------------
__device__ __forceinline__ uint32_t smem_u32(const void* p) {
    return (uint32_t)__cvta_generic_to_shared(p);
}
__device__ __forceinline__ void cp_async16(uint32_t s, const void* g) {
    asm volatile("cp.async.cg.shared.global [%0], [%1], 16;" :: "r"(s), "l"(g) : "memory");
}
__device__ __forceinline__ void cp_commit() {
    asm volatile("cp.async.commit_group;" ::: "memory");
}
template <int N> __device__ __forceinline__ void cp_wait() {
    asm volatile("cp.async.wait_group %0;" :: "n"(N) : "memory");
}
__device__ __forceinline__ uint32_t cvt_bf16x2(float lo, float hi) {
    uint32_t r;
    asm("cvt.rn.bf16x2.f32 %0, %1, %2;" : "=r"(r) : "f"(hi), "f"(lo));
    return r;
}
__device__ __forceinline__ void ldsm_x4(uint32_t* r, uint32_t addr) {
    asm volatile("ldmatrix.sync.aligned.m8n8.x4.shared.b16 {%0,%1,%2,%3}, [%4];"
                 : "=r"(r[0]), "=r"(r[1]), "=r"(r[2]), "=r"(r[3]) : "r"(addr));
}
__device__ __forceinline__ void ldsm_x2(uint32_t* r, uint32_t addr) {
    asm volatile("ldmatrix.sync.aligned.m8n8.x2.shared.b16 {%0,%1}, [%2];"
                 : "=r"(r[0]), "=r"(r[1]) : "r"(addr));
}
__device__ __forceinline__ void mma_bf16(float* d, const uint32_t* a,
                                         uint32_t b0, uint32_t b1) {
    asm volatile(
        "mma.sync.aligned.m16n8k16.row.col.f32.bf16.bf16.f32 "
        "{%0,%1,%2,%3}, {%4,%5,%6,%7}, {%8,%9}, {%0,%1,%2,%3};"
        : "+f"(d[0]), "+f"(d[1]), "+f"(d[2]), "+f"(d[3])
        : "r"(a[0]), "r"(a[1]), "r"(a[2]), "r"(a[3]), "r"(b0), "r"(b1));
}

// ---------------------------------------------------------------------------
// Kernel 1: normalize+scale weights; bf16 hi/lo split; 16B-swizzled image
// ---------------------------------------------------------------------------
__global__ void prep_weights_kernel(const float* __restrict__ w,
                                    const float* __restrict__ asf) {
    int c = blockIdx.x;
    int d = threadIdx.x;
    float v = w[c * D + d];

    __shared__ float red[D];
    red[d] = v * v;
    __syncthreads();
    #pragma unroll
    for (int s = D / 2; s > 0; s >>= 1) {
        if (d < s) red[d] += red[d + s];
        __syncthreads();
    }
    float scale = asf[c] * RANGE_EXTENDER / fmaxf(sqrtf(red[0]), EPS);
    float wn = v * scale;

    __nv_bfloat16 h = __float2bfloat16(wn);
    __nv_bfloat16 l = __float2bfloat16(wn - __bfloat162float(h));

    int t  = d >> 5;
    int kl = d & 31;
    int kp = kl >> 1;
    int chunk = kp >> 2;
    int word  = kp & 3;
    int inner = ((chunk ^ ((c >> 1) & 3)) << 4) + (word << 2) + (kl & 1) * 2;

    size_t hb = ((size_t)(t * 2 + 0) * C + c) * 64 + inner;
    size_t lb = ((size_t)(t * 2 + 1) * C + c) * 64 + inner;
    *reinterpret_cast<__nv_bfloat16*>(g_wimg + hb) = h;
    *reinterpret_cast<__nv_bfloat16*>(g_wimg + lb) = l;
}

// ---------------------------------------------------------------------------
// Kernel 2: bf16 mma.sync GEMM, 3-term split, register-dieted for 3 CTAs/SM.
// x staged via single cp.async raw buffer; A per-m, B streamed per u-group.
// ---------------------------------------------------------------------------
__global__ __launch_bounds__(NTHREADS, 3)
void coshead_main_kernel(const float* __restrict__ x, float* __restrict__ out) {
    extern __shared__ char smem[];
    const uint32_t sb = smem_u32(smem);

    const int tid  = threadIdx.x;
    const int lane = tid & 31;
    const int wid  = tid >> 5;
    const int pxbase = (wid & 3) * 32;
    const int chbase = (wid >> 2) * 40;
    const int r = lane >> 2;
    const int q = lane & 3;

    const int tile    = blockIdx.x;
    const int b       = (tile * PXT) >> 14;
    const int hw_base = (tile * PXT) & (HW - 1);
    const float4* gx4 = reinterpret_cast<const float4*>(
        x + ((size_t)b * D) * HW + hw_base);

    const int cpx  = tid & 127;      // conversion pixel
    const int half = tid >> 7;       // conversion k-half
    float n2 = 0.0f;

    auto stage_xr = [&](int t) {
        uint32_t xd = sb + S_XR;
        #pragma unroll
        for (int i = tid, j = 0; j < 4; j++, i += NTHREADS) {
            int row = i >> 5, col = i & 31;
            cp_async16(xd + row * 512 + col * 16,
                       &gx4[(size_t)(t * KC + row) * (HW / 4) + col]);
        }
        cp_commit();
    };
    auto stage_w = [&](int t, int buf) {
        const unsigned char* ws = g_wimg + (size_t)t * 10240;
        uint32_t wd = sb + S_W + buf * 10240;
        #pragma unroll
        for (int i = tid, j = 0; j < 3; j++, i += NTHREADS)
            if (i < 640) cp_async16(wd + i * 16, ws + i * 16);
        cp_commit();
    };

    // convert chunk in XR into XS[buf]
    auto convert = [&](int buf) {
        const float* xr = reinterpret_cast<const float*>(smem + S_XR);
        char* xh = smem + S_XS + buf * 16384;
        char* xl = xh + 8192;
        #pragma unroll
        for (int c2 = 0; c2 < 2; c2++) {
            int chunk = half * 2 + c2;
            uint32_t wh[4], wl[4];
            #pragma unroll
            for (int i = 0; i < 4; i++) {
                int k0 = chunk * 8 + i * 2;
                float v0 = xr[k0 * PXT + cpx];
                float v1 = xr[(k0 + 1) * PXT + cpx];
                n2 = fmaf(v0, v0, n2);
                n2 = fmaf(v1, v1, n2);
                __nv_bfloat16 h0 = __float2bfloat16(v0);
                __nv_bfloat16 h1 = __float2bfloat16(v1);
                float l0 = v0 - __bfloat162float(h0);
                float l1 = v1 - __bfloat162float(h1);
                wh[i] = ((uint32_t)__bfloat16_as_ushort(h1) << 16)
                      | __bfloat16_as_ushort(h0);
                wl[i] = cvt_bf16x2(l0, l1);
            }
            int addr = cpx * 64 + ((chunk ^ ((cpx >> 1) & 3)) << 4);
            *reinterpret_cast<uint4*>(xh + addr) = make_uint4(wh[0], wh[1], wh[2], wh[3]);
            *reinterpret_cast<uint4*>(xl + addr) = make_uint4(wl[0], wl[1], wl[2], wl[3]);
        }
    };

    float acc[2][5][4];
    #pragma unroll
    for (int m = 0; m < 2; m++)
        #pragma unroll
        for (int n = 0; n < 5; n++)
            #pragma unroll
            for (int k = 0; k < 4; k++) acc[m][n][k] = 0.0f;

    // prologue: XR(0), W(0); convert(0); XR(1)
    stage_xr(0);                 // G: XR0
    stage_w(0, 0);               // G: W0
    cp_wait<1>();                // XR0 done
    __syncthreads();
    convert(0);
    __syncthreads();
    stage_xr(1);                 // G: XR1

    const int mat = lane >> 3, rowi = lane & 7;

    for (int t = 0; t < NT; t++) {
        const int buf = t & 1;
        if (t + 1 < NT) { stage_w(t + 1, buf ^ 1); cp_wait<1>(); }
        else           { cp_wait<0>(); }
        __syncthreads();   // XS[buf] converted; W[buf] staged; XR(t+1) staged

        const uint32_t xhb = sb + S_XS + buf * 16384;
        const uint32_t whb = sb + S_W + buf * 10240;

        #pragma unroll
        for (int s = 0; s < 2; s++) {
            #pragma unroll
            for (int m = 0; m < 2; m++) {
                // A fragments for this m-tile (hi + lo)
                uint32_t ah[4], al_[4];
                {
                    int px = pxbase + m * 16 + ((mat & 1) << 3) + rowi;
                    int ck = 2 * s + (mat >> 1);
                    uint32_t a = xhb + px * 64 + ((ck ^ ((px >> 1) & 3)) << 4);
                    ldsm_x4(ah, a);
                    ldsm_x4(al_, a + 8192);
                }
                // B streamed per u-group of 2 n-tiles
                #pragma unroll
                for (int u = 0; u < 2; u++) {
                    int cc = chbase + u * 16 + ((mat >> 1) << 3) + rowi;
                    int ck = 2 * s + (mat & 1);
                    uint32_t a = whb + cc * 64 + ((ck ^ ((cc >> 1) & 3)) << 4);
                    uint32_t bb[4];
                    ldsm_x4(bb, a);                  // hi: n-tiles 2u, 2u+1
                    mma_bf16(acc[m][2 * u],     ah,  bb[0], bb[1]);
                    mma_bf16(acc[m][2 * u],     al_, bb[0], bb[1]);
                    mma_bf16(acc[m][2 * u + 1], ah,  bb[2], bb[3]);
                    mma_bf16(acc[m][2 * u + 1], al_, bb[2], bb[3]);
                    ldsm_x4(bb, a + 5120);           // lo
                    mma_bf16(acc[m][2 * u],     ah,  bb[0], bb[1]);
                    mma_bf16(acc[m][2 * u + 1], ah,  bb[2], bb[3]);
                }
                {   // n-tile 4 (channels 32..39 of the 40-block)
                    int cc = chbase + 32 + rowi;
                    int ck = 2 * s + (mat & 1);
                    uint32_t a = whb + cc * 64 + ((ck ^ ((cc >> 1) & 3)) << 4);
                    uint32_t bb[2];
                    ldsm_x2(bb, a);
                    mma_bf16(acc[m][4], ah,  bb[0], bb[1]);
                    mma_bf16(acc[m][4], al_, bb[0], bb[1]);
                    ldsm_x2(bb, a + 5120);
                    mma_bf16(acc[m][4], ah,  bb[0], bb[1]);
                }
            }
        }

        if (t + 1 < NT) convert(buf ^ 1);    // XR(t+1) -> XS[buf^1]
        __syncthreads();                     // all XR reads done
        if (t + 2 < NT) stage_xr(t + 2);     // refill XR under next MMA phase
    }

    // ---- norms ----
    float* np = reinterpret_cast<float*>(smem + S_NP);
    float* ni = reinterpret_cast<float*>(smem + S_NI);
    np[half * 128 + cpx] = n2;
    __syncthreads();
    if (tid < 128)
        ni[tid] = 1.0f / fmaxf(sqrtf(np[tid] + np[128 + tid]), EPS);
    __syncthreads();

    // ---- epilogue ----
    float* ob = out + ((size_t)b * C) * HW + hw_base;
    #pragma unroll
    for (int m = 0; m < 2; m++) {
        int p0 = pxbase + m * 16 + r;
        int p1 = p0 + 8;
        float i0 = ni[p0], i1 = ni[p1];
        #pragma unroll
        for (int n = 0; n < 5; n++) {
            int ch = chbase + n * 8 + q * 2;
            ob[(size_t)ch * HW + p0]       = acc[m][n][0] * i0;
            ob[(size_t)(ch + 1) * HW + p0] = acc[m][n][1] * i0;
            ob[(size_t)ch * HW + p1]       = acc[m][n][2] * i1;
            ob[(size_t)(ch + 1) * HW + p1] = acc[m][n][3] * i1;
        }
    }
}

// ---------------------------------------------------------------------------
// Launch
// ---------------------------------------------------------------------------
extern "C" void kernel_launch(void* const* d_in, const int* in_sizes, int n_in,
                              void* d_out, int out_size) {
    const float* x   = (const float*)d_in[0];
    const float* w   = (const float*)d_in[1];
    const float* asf = (const float*)d_in[2];
    float* out = (float*)d_out;

    cudaFuncSetAttribute(coshead_main_kernel,
                         cudaFuncAttributeMaxDynamicSharedMemorySize, S_TOTAL);
    prep_weights_kernel<<<C, D>>>(w, asf);
    coshead_main_kernel<<<NPIX / PXT, NTHREADS, S_TOTAL>>>(x, out);
}

// round 12
// speedup vs baseline: 1.0408x; 1.0408x over previous
#include <cuda_runtime.h>
#include <cuda_bf16.h>
#include <cstdint>

#define B 8
#define D 256
#define HW (128 * 128)
#define C 80
#define NPIX (B * HW)
#define RANGE_EXTENDER 10.0f
#define EPS 1e-8f

#define KC 32                 // K per chunk
#define NT (D / KC)           // 8 chunks
#define PXT 128               // pixels per CTA (= M)
#define NTHREADS 256          // 8 warps: 4 px-groups x 2 ch-groups

// smem map (dynamic): whole W image resident + double-buffered XS
#define S_W   0               // 8 chunks x 10240B = 81920
#define S_XS  81920           // 2 x (xh 8KB + xl 8KB) = 32768
#define S_NP  S_XS            // norm partials alias XS after mainloop
#define S_NI  (S_XS + 1024)
#define S_TOTAL 114688

// Pre-split weight image, 16B-swizzled: [chunk t][hl][c][64B]
__device__ __align__(16) unsigned char g_wimg[NT * 2 * C * 64];

// ---------------------------------------------------------------------------
// helpers
// ---------------------------------------------------------------------------
__device__ __forceinline__ uint32_t smem_u32(const void* p) {
    return (uint32_t)__cvta_generic_to_shared(p);
}
__device__ __forceinline__ void cp_async16(uint32_t s, const void* g) {
    asm volatile("cp.async.cg.shared.global [%0], [%1], 16;" :: "r"(s), "l"(g) : "memory");
}
__device__ __forceinline__ void cp_commit() {
    asm volatile("cp.async.commit_group;" ::: "memory");
}
template <int N> __device__ __forceinline__ void cp_wait() {
    asm volatile("cp.async.wait_group %0;" :: "n"(N) : "memory");
}
__device__ __forceinline__ uint32_t cvt_bf16x2(float lo, float hi) {
    uint32_t r;
    asm("cvt.rn.bf16x2.f32 %0, %1, %2;" : "=r"(r) : "f"(hi), "f"(lo));
    return r;
}
__device__ __forceinline__ void ldsm_x4(uint32_t* r, uint32_t addr) {
    asm volatile("ldmatrix.sync.aligned.m8n8.x4.shared.b16 {%0,%1,%2,%3}, [%4];"
                 : "=r"(r[0]), "=r"(r[1]), "=r"(r[2]), "=r"(r[3]) : "r"(addr));
}
__device__ __forceinline__ void ldsm_x2(uint32_t* r, uint32_t addr) {
    asm volatile("ldmatrix.sync.aligned.m8n8.x2.shared.b16 {%0,%1}, [%2];"
                 : "=r"(r[0]), "=r"(r[1]) : "r"(addr));
}
__device__ __forceinline__ void mma_bf16(float* d, const uint32_t* a,
                                         uint32_t b0, uint32_t b1) {
    asm volatile(
        "mma.sync.aligned.m16n8k16.row.col.f32.bf16.bf16.f32 "
        "{%0,%1,%2,%3}, {%4,%5,%6,%7}, {%8,%9}, {%0,%1,%2,%3};"
        : "+f"(d[0]), "+f"(d[1]), "+f"(d[2]), "+f"(d[3])
        : "r"(a[0]), "r"(a[1]), "r"(a[2]), "r"(a[3]), "r"(b0), "r"(b1));
}

// ---------------------------------------------------------------------------
// Kernel 1: normalize+scale weights; bf16 hi/lo split; 16B-swizzled image
// ---------------------------------------------------------------------------
__global__ void prep_weights_kernel(const float* __restrict__ w,
                                    const float* __restrict__ asf) {
    int c = blockIdx.x;
    int d = threadIdx.x;
    float v = w[c * D + d];

    __shared__ float red[D];
    red[d] = v * v;
    __syncthreads();
    #pragma unroll
    for (int s = D / 2; s > 0; s >>= 1) {
        if (d < s) red[d] += red[d + s];
        __syncthreads();
    }
    float scale = asf[c] * RANGE_EXTENDER / fmaxf(sqrtf(red[0]), EPS);
    float wn = v * scale;

    __nv_bfloat16 h = __float2bfloat16(wn);
    __nv_bfloat16 l = __float2bfloat16(wn - __bfloat162float(h));

    int t  = d >> 5;
    int kl = d & 31;
    int kp = kl >> 1;
    int chunk = kp >> 2;
    int word  = kp & 3;
    int inner = ((chunk ^ ((c >> 1) & 3)) << 4) + (word << 2) + (kl & 1) * 2;

    size_t hb = ((size_t)(t * 2 + 0) * C + c) * 64 + inner;
    size_t lb = ((size_t)(t * 2 + 1) * C + c) * 64 + inner;
    *reinterpret_cast<__nv_bfloat16*>(g_wimg + hb) = h;
    *reinterpret_cast<__nv_bfloat16*>(g_wimg + lb) = l;
}

// ---------------------------------------------------------------------------
// Kernel 2: bf16 mma.sync GEMM, 3-term split. W fully smem-resident;
// one barrier per chunk; x prefetched gmem->regs under the MMA phase.
// ---------------------------------------------------------------------------
__global__ __launch_bounds__(NTHREADS, 2)
void coshead_main_kernel(const float* __restrict__ x, float* __restrict__ out) {
    extern __shared__ char smem[];
    const uint32_t sb = smem_u32(smem);

    const int tid  = threadIdx.x;
    const int lane = tid & 31;
    const int wid  = tid >> 5;
    const int pxbase = (wid & 3) * 32;
    const int chbase = (wid >> 2) * 40;
    const int r = lane >> 2;
    const int q = lane & 3;

    const int tile    = blockIdx.x;
    const int b       = (tile * PXT) >> 14;
    const int hw_base = (tile * PXT) & (HW - 1);
    const float* xg = x + ((size_t)b * D) * HW + hw_base;

    const int cpx  = tid & 127;      // conversion pixel
    const int half = tid >> 7;       // conversion k-half
    float n2 = 0.0f;

    // convert 16 x values (this thread's half of a chunk) into XS[buf]
    auto convert = [&](const float* xv, int buf) {
        char* xh = smem + S_XS + buf * 16384;
        char* xl = xh + 8192;
        #pragma unroll
        for (int c2 = 0; c2 < 2; c2++) {
            int chunk = half * 2 + c2;
            uint32_t wh[4], wl[4];
            #pragma unroll
            for (int i = 0; i < 4; i++) {
                float v0 = xv[c2 * 8 + i * 2];
                float v1 = xv[c2 * 8 + i * 2 + 1];
                n2 = fmaf(v0, v0, n2);
                n2 = fmaf(v1, v1, n2);
                __nv_bfloat16 h0 = __float2bfloat16(v0);
                __nv_bfloat16 h1 = __float2bfloat16(v1);
                float l0 = v0 - __bfloat162float(h0);
                float l1 = v1 - __bfloat162float(h1);
                wh[i] = ((uint32_t)__bfloat16_as_ushort(h1) << 16)
                      | __bfloat16_as_ushort(h0);
                wl[i] = cvt_bf16x2(l0, l1);
            }
            int addr = cpx * 64 + ((chunk ^ ((cpx >> 1) & 3)) << 4);
            *reinterpret_cast<uint4*>(xh + addr) = make_uint4(wh[0], wh[1], wh[2], wh[3]);
            *reinterpret_cast<uint4*>(xl + addr) = make_uint4(wl[0], wl[1], wl[2], wl[3]);
        }
    };

    float acc[2][5][4];
    #pragma unroll
    for (int m = 0; m < 2; m++)
        #pragma unroll
        for (int n = 0; n < 5; n++)
            #pragma unroll
            for (int k = 0; k < 4; k++) acc[m][n][k] = 0.0f;

    // ---- prologue: stage ALL of W (80KB) + convert chunk 0 ----
    #pragma unroll 4
    for (int i = tid; i < 5120; i += NTHREADS)
        cp_async16(sb + S_W + i * 16, g_wimg + (size_t)i * 16);
    cp_commit();
    {
        float xv[16];
        const float* xr = xg + (size_t)(half * 16) * HW + cpx;
        #pragma unroll
        for (int j = 0; j < 16; j++) xv[j] = xr[(size_t)j * HW];
        convert(xv, 0);
    }
    cp_wait<0>();
    __syncthreads();   // W resident, XS[0] converted

    const int mat = lane >> 3, rowi = lane & 7;

    for (int t = 0; t < NT; t++) {
        const int buf = t & 1;

        // prefetch next chunk's x into registers (drains under the MMAs)
        float xv[16];
        if (t + 1 < NT) {
            const float* xr = xg + (size_t)((t + 1) * KC + half * 16) * HW + cpx;
            #pragma unroll
            for (int j = 0; j < 16; j++) xv[j] = xr[(size_t)j * HW];
        }

        const uint32_t xhb = sb + S_XS + buf * 16384;
        const uint32_t whb = sb + S_W + t * 10240;

        #pragma unroll
        for (int s = 0; s < 2; s++) {
            uint32_t ah[2][4], al_[2][4];
            #pragma unroll
            for (int m = 0; m < 2; m++) {
                int px = pxbase + m * 16 + ((mat & 1) << 3) + rowi;
                int ck = 2 * s + (mat >> 1);
                uint32_t a = xhb + px * 64 + ((ck ^ ((px >> 1) & 3)) << 4);
                ldsm_x4(ah[m], a);
                ldsm_x4(al_[m], a + 8192);
            }
            uint32_t bh[5][2], bl[5][2];
            #pragma unroll
            for (int u = 0; u < 2; u++) {
                int cc = chbase + u * 16 + ((mat >> 1) << 3) + rowi;
                int ck = 2 * s + (mat & 1);
                uint32_t a = whb + cc * 64 + ((ck ^ ((cc >> 1) & 3)) << 4);
                uint32_t rr[4];
                ldsm_x4(rr, a);
                bh[2 * u][0] = rr[0]; bh[2 * u][1] = rr[1];
                bh[2 * u + 1][0] = rr[2]; bh[2 * u + 1][1] = rr[3];
                ldsm_x4(rr, a + 5120);
                bl[2 * u][0] = rr[0]; bl[2 * u][1] = rr[1];
                bl[2 * u + 1][0] = rr[2]; bl[2 * u + 1][1] = rr[3];
            }
            {
                int cc = chbase + 32 + rowi;
                int ck = 2 * s + (mat & 1);
                uint32_t a = whb + cc * 64 + ((ck ^ ((cc >> 1) & 3)) << 4);
                uint32_t rr[2];
                ldsm_x2(rr, a);
                bh[4][0] = rr[0]; bh[4][1] = rr[1];
                ldsm_x2(rr, a + 5120);
                bl[4][0] = rr[0]; bl[4][1] = rr[1];
            }
            #pragma unroll
            for (int n = 0; n < 5; n++)
                #pragma unroll
                for (int m = 0; m < 2; m++) {
                    mma_bf16(acc[m][n], ah[m],  bh[n][0], bh[n][1]);
                    mma_bf16(acc[m][n], al_[m], bh[n][0], bh[n][1]);
                    mma_bf16(acc[m][n], ah[m],  bl[n][0], bl[n][1]);
                }
        }

        // convert next chunk into the other buffer (overlaps tensor drain)
        if (t + 1 < NT) convert(xv, buf ^ 1);
        __syncthreads();   // single barrier per chunk
    }

    // ---- norms (aliased into XS area — safe after final barrier) ----
    float* np = reinterpret_cast<float*>(smem + S_NP);
    float* ni = reinterpret_cast<float*>(smem + S_NI);
    np[half * 128 + cpx] = n2;
    __syncthreads();
    if (tid < 128)
        ni[tid] = 1.0f / fmaxf(sqrtf(np[tid] + np[128 + tid]), EPS);
    __syncthreads();

    // ---- epilogue ----
    float* ob = out + ((size_t)b * C) * HW + hw_base;
    #pragma unroll
    for (int m = 0; m < 2; m++) {
        int p0 = pxbase + m * 16 + r;
        int p1 = p0 + 8;
        float i0 = ni[p0], i1 = ni[p1];
        #pragma unroll
        for (int n = 0; n < 5; n++) {
            int ch = chbase + n * 8 + q * 2;
            ob[(size_t)ch * HW + p0]       = acc[m][n][0] * i0;
            ob[(size_t)(ch + 1) * HW + p0] = acc[m][n][1] * i0;
            ob[(size_t)ch * HW + p1]       = acc[m][n][2] * i1;
            ob[(size_t)(ch + 1) * HW + p1] = acc[m][n][3] * i1;
        }
    }
}

// ---------------------------------------------------------------------------
// Launch
// ---------------------------------------------------------------------------
extern "C" void kernel_launch(void* const* d_in, const int* in_sizes, int n_in,
                              void* d_out, int out_size) {
    const float* x   = (const float*)d_in[0];
    const float* w   = (const float*)d_in[1];
    const float* asf = (const float*)d_in[2];
    float* out = (float*)d_out;

    cudaFuncSetAttribute(coshead_main_kernel,
                         cudaFuncAttributeMaxDynamicSharedMemorySize, S_TOTAL);
    prep_weights_kernel<<<C, D>>>(w, asf);
    coshead_main_kernel<<<NPIX / PXT, NTHREADS, S_TOTAL>>>(x, out);
}